// round 1
// baseline (speedup 1.0000x reference)
#include <cuda_runtime.h>

#define COLS 8192
#define TPB  256
#define EPT  32            // elements per thread: 256*32 = 8192
#define NW   (TPB / 32)    // 8 warps

// Single-instruction hardware exp2 (MUFU.EX2), ~2 ulp. ftz is fine at 1e-3 tol.
__device__ __forceinline__ float ex2f(float x) {
    float y;
    asm("ex2.approx.ftz.f32 %0, %1;" : "=f"(y) : "f"(x));
    return y;
}

// Block reduction: warp shfl tree + one __syncthreads + broadcast read.
// Caller alternates between two shared buffers (double-buffer removes the
// WAR barrier; safety: reads of buf[p] precede the caller's next barrier).
__device__ __forceinline__ float blk_reduce(float v, float* buf, int warp, int lane) {
    #pragma unroll
    for (int o = 16; o; o >>= 1) v += __shfl_xor_sync(0xffffffffu, v, o);
    if (lane == 0) buf[warp] = v;
    __syncthreads();
    float r = buf[0];
    #pragma unroll
    for (int w = 1; w < NW; w++) r += buf[w];
    return r;
}

__global__ void __launch_bounds__(TPB)
normalizer_kernel(const float* __restrict__ score,
                  const int*   __restrict__ mask,
                  float*       __restrict__ out) {
    __shared__ float buf[2][NW];

    const int tid  = threadIdx.x;
    const int lane = tid & 31;
    const int warp = tid >> 5;
    const size_t base = (size_t)blockIdx.x * COLS;

    const float4* s4 = (const float4*)(score + base);
    const int4*   m4 = (const int4*)(mask + base);

    // Load row into registers, apply mask as large-negative (exp -> 0,
    // relu(s+a) -> 0, gamma -> 0; avoids inf-arithmetic hazards).
    float s[EPT];
    float cnt = 0.0f;
    #pragma unroll
    for (int i = 0; i < EPT / 4; i++) {
        float4 v = s4[i * TPB + tid];
        int4   m = m4[i * TPB + tid];
        s[4*i+0] = m.x ? v.x : -1e30f;  cnt += m.x ? 1.0f : 0.0f;
        s[4*i+1] = m.y ? v.y : -1e30f;  cnt += m.y ? 1.0f : 0.0f;
        s[4*i+2] = m.z ? v.z : -1e30f;  cnt += m.z ? 1.0f : 0.0f;
        s[4*i+3] = m.w ? v.w : -1e30f;  cnt += m.w ? 1.0f : 0.0f;
    }

    int pb = 0;
    const float k = 0.1f * blk_reduce(cnt, buf[pb], warp, lane); pb ^= 1;

    const float L2E = 1.44269504088896340736f;
    // theta_t = max(0.7^t * 4, 0.3): distinct for t=0..7, then 0.3 for t=8..19
    const float TH[8] = {4.0f, 2.8f, 1.96f, 1.372f, 0.9604f,
                         0.67228f, 0.470596f, 0.3294172f};

    float a;
    // ---- iteration 0: b = 0 exactly -> term = exp(s_i / th0) ----
    {
        const float K0 = L2E / 4.0f;
        float l0 = 0.f, l1 = 0.f, l2 = 0.f, l3 = 0.f;
        #pragma unroll
        for (int j = 0; j < EPT; j += 4) {
            l0 += ex2f(s[j+0] * K0);
            l1 += ex2f(s[j+1] * K0);
            l2 += ex2f(s[j+2] * K0);
            l3 += ex2f(s[j+3] * K0);
        }
        float sum = blk_reduce((l0 + l1) + (l2 + l3), buf[pb], warp, lane); pb ^= 1;
        a = TH[0] * __logf(__fdividef(k, sum + 1e-20f));
    }

    // ---- iterations 1..7 (annealed thetas): arg = min(s_i, -a) / th ----
    #pragma unroll
    for (int t = 1; t < 8; t++) {
        const float Kt = L2E / TH[t];   // folds to a constant (unrolled)
        const float na = -a;
        float l0 = 0.f, l1 = 0.f, l2 = 0.f, l3 = 0.f;
        #pragma unroll
        for (int j = 0; j < EPT; j += 4) {
            l0 += ex2f(fminf(s[j+0], na) * Kt);
            l1 += ex2f(fminf(s[j+1], na) * Kt);
            l2 += ex2f(fminf(s[j+2], na) * Kt);
            l3 += ex2f(fminf(s[j+3], na) * Kt);
        }
        float sum = blk_reduce((l0 + l1) + (l2 + l3), buf[pb], warp, lane); pb ^= 1;
        a = TH[t] * __logf(__fdividef(k, sum + 1e-20f));
    }

    // ---- convert in place: s_j := exp(s_j / 0.3)  (monotone, so min commutes) ----
    const float K03 = L2E / 0.3f;
    #pragma unroll
    for (int j = 0; j < EPT; j++) s[j] = ex2f(s[j] * K03);

    // ---- iterations 8..19 (theta = 0.3, constant): term = min(e_j, exp(-a/0.3)) ----
    #pragma unroll 1
    for (int t = 0; t < 12; t++) {
        const float c = ex2f(-a * K03);
        float l0 = 0.f, l1 = 0.f, l2 = 0.f, l3 = 0.f;
        #pragma unroll
        for (int j = 0; j < EPT; j += 4) {
            l0 += fminf(s[j+0], c);
            l1 += fminf(s[j+1], c);
            l2 += fminf(s[j+2], c);
            l3 += fminf(s[j+3], c);
        }
        float sum = blk_reduce((l0 + l1) + (l2 + l3), buf[pb], warp, lane); pb ^= 1;
        a = 0.3f * __logf(__fdividef(k, sum + 1e-20f));
    }

    // ---- gamma = exp(min(s_i + a, 0)/0.3) = min(e_i * exp(a/0.3), 1) ----
    const float g = ex2f(a * K03);
    float4* o4 = (float4*)(out + base);
    #pragma unroll
    for (int i = 0; i < EPT / 4; i++) {
        float4 r;
        r.x = fminf(s[4*i+0] * g, 1.0f);
        r.y = fminf(s[4*i+1] * g, 1.0f);
        r.z = fminf(s[4*i+2] * g, 1.0f);
        r.w = fminf(s[4*i+3] * g, 1.0f);
        o4[i * TPB + tid] = r;
    }
}

extern "C" void kernel_launch(void* const* d_in, const int* in_sizes, int n_in,
                              void* d_out, int out_size) {
    const float* score = (const float*)d_in[0];
    const int*   mask  = (const int*)d_in[1];
    float*       out   = (float*)d_out;
    int rows = in_sizes[0] / COLS;
    normalizer_kernel<<<rows, TPB>>>(score, mask, out);
}